// round 10
// baseline (speedup 1.0000x reference)
#include <cuda_runtime.h>
#include <cuda_bf16.h>
#include <math.h>
#include <stdint.h>

// ---------------- problem constants ----------------
#define NB     32
#define NFEAT  64
#define NH     256
#define NP     96
#define TM     32           // rows per tile
#define NT     512
#define PS     100          // padded row stride (floats) for pp

#define TWO_PI_F   6.2831853071795864769f
#define MIN_WH     1e-3f
#define MIN_D      1e-3f
#define DERIV_OFF  0.5413248546129181f     // log(e-1)
#define SIZE_SCALE (1.0f - 1e-3f * 32.0f)

// ---- smem layout (bytes) ----
#define SM_W1H   0          // W1T hi [256 n][64 k bf16 = 128B rows, SWZ128]  32KB
#define SM_W1L   32768
#define SM_W2H   65536      // W2T hi [96 n][256 k bf16 = 512B rows, SWZ512]  48KB
#define SM_W2L   114688
#define SM_X     163840     // X single buf: hi 4KB @0, lo 4KB @4096 (SWZ128)  8KB
#define SM_HH    172032     // h hi [32 r][256 bf16, SWZ512]                  16KB
#define SM_HL    188416     // h lo                                           16KB
#define SM_PP0   204800     // spline params f32[32][PS], buffer 0          12.8KB
#define SM_PP1   217600     // buffer 1                                     12.8KB
#define SM_B1    230400     // b1 f32[256]
#define SM_B2    231424     // b2 f32[96]
#define SM_TOTAL 231808

#define SWZ128(o) ((uint32_t)(o) ^ (((uint32_t)(o) >> 3) & 0x70u))
#define SWZ512(o) ((uint32_t)(o) ^ (((uint32_t)(o) >> 5) & 0x70u))

// ---------------- pre-split weights (device globals) ----------------
__device__ uint32_t g_W1T_hi[NH * NFEAT / 2];   // [n][kpair]
__device__ uint32_t g_W1T_lo[NH * NFEAT / 2];
__device__ uint32_t g_W2T_hi[NP * NH / 2];      // [n][kpair]
__device__ uint32_t g_W2T_lo[NP * NH / 2];

// ---------------- helpers ----------------
static __device__ __forceinline__ uint32_t smem_u32(const void* p) {
    uint32_t a;
    asm("{ .reg .u64 t; cvta.to.shared.u64 t, %1; cvt.u32.u64 %0, t; }" : "=r"(a) : "l"(p));
    return a;
}
static __device__ __forceinline__ void ldsm_x4(uint32_t addr, uint32_t r[4]) {
    asm volatile("ldmatrix.sync.aligned.m8n8.x4.shared.b16 {%0,%1,%2,%3}, [%4];"
                 : "=r"(r[0]), "=r"(r[1]), "=r"(r[2]), "=r"(r[3]) : "r"(addr));
}
static __device__ __forceinline__ void ldsm_x2(uint32_t addr, uint32_t r[2]) {
    asm volatile("ldmatrix.sync.aligned.m8n8.x2.shared.b16 {%0,%1}, [%2];"
                 : "=r"(r[0]), "=r"(r[1]) : "r"(addr));
}
static __device__ __forceinline__ void mma16816(float c[4], const uint32_t a[4], const uint32_t b[2]) {
    asm volatile("mma.sync.aligned.m16n8k16.row.col.f32.bf16.bf16.f32 "
                 "{%0,%1,%2,%3}, {%4,%5,%6,%7}, {%8,%9}, {%0,%1,%2,%3};"
                 : "+f"(c[0]), "+f"(c[1]), "+f"(c[2]), "+f"(c[3])
                 : "r"(a[0]), "r"(a[1]), "r"(a[2]), "r"(a[3]), "r"(b[0]), "r"(b[1]));
}
static __device__ __forceinline__ uint32_t pack_hi(float v0, float v1) {
    __nv_bfloat16 h0 = __float2bfloat16_rn(v0), h1 = __float2bfloat16_rn(v1);
    return (uint32_t)__bfloat16_as_ushort(h0) | ((uint32_t)__bfloat16_as_ushort(h1) << 16);
}
static __device__ __forceinline__ uint32_t pack_lo(float v0, float v1) {
    __nv_bfloat16 h0 = __float2bfloat16_rn(v0), h1 = __float2bfloat16_rn(v1);
    __nv_bfloat16 l0 = __float2bfloat16_rn(v0 - __bfloat162float(h0));
    __nv_bfloat16 l1 = __float2bfloat16_rn(v1 - __bfloat162float(h1));
    return (uint32_t)__bfloat16_as_ushort(l0) | ((uint32_t)__bfloat16_as_ushort(l1) << 16);
}
static __device__ __forceinline__ float softplus_f(float x) {
    return (x > 0.0f) ? (x + log1pf(expf(-x))) : log1pf(expf(x));
}

// warp-per-row circular RQ spline (lane = bin); pp row rr, write global row
static __device__ __forceinline__ void spline_row(const float* pp, int rr, int row, int l,
                                                  const float* __restrict__ theta,
                                                  float* __restrict__ out, int B)
{
    const unsigned FULL = 0xffffffffu;
    float th_in = theta[row];
    float uw = pp[rr * PS + l];
    float uh = pp[rr * PS + NB + l];
    float ud = pp[rr * PS + 2 * NB + l] + DERIV_OFF;

    float mw = uw, mh = uh;
    #pragma unroll
    for (int o = 16; o; o >>= 1) {
        mw = fmaxf(mw, __shfl_xor_sync(FULL, mw, o));
        mh = fmaxf(mh, __shfl_xor_sync(FULL, mh, o));
    }
    float ew = expf(uw - mw), eh = expf(uh - mh);
    float sw = ew, sh = eh;
    #pragma unroll
    for (int o = 16; o; o >>= 1) {
        sw += __shfl_xor_sync(FULL, sw, o);
        sh += __shfl_xor_sync(FULL, sh, o);
    }
    float szw = MIN_WH + SIZE_SCALE * (ew / sw);
    float szh = MIN_WH + SIZE_SCALE * (eh / sh);

    float cw = szw, chs = szh;
    #pragma unroll
    for (int o = 1; o < 32; o <<= 1) {
        float a = __shfl_up_sync(FULL, cw,  o);
        float b = __shfl_up_sync(FULL, chs, o);
        if (l >= o) { cw += a; chs += b; }
    }

    float kw = (l == 31) ? TWO_PI_F : TWO_PI_F * cw;
    float kh = (l == 31) ? TWO_PI_F : TWO_PI_F * chs;

    unsigned bal = __ballot_sync(FULL, th_in >= kw);
    int bin = __popc(bal);
    if (bin > NB - 1) bin = NB - 1;
    int lo = (bin > 0) ? bin - 1 : 0;

    float cw_hi = __shfl_sync(FULL, kw, bin);
    float cw_lo = __shfl_sync(FULL, kw, lo);
    float ch_hi = __shfl_sync(FULL, kh, bin);
    float ch_lo = __shfl_sync(FULL, kh, lo);
    if (bin == 0) { cw_lo = 0.0f; ch_lo = 0.0f; }

    float in_w = cw_hi - cw_lo;
    float in_h = ch_hi - ch_lo;

    float dsp  = MIN_D + softplus_f(ud);
    float d_k  = __shfl_sync(FULL, dsp, bin);
    float d_k1 = __shfl_sync(FULL, dsp, (bin + 1) & 31);

    float delta = in_h / in_w;
    float th    = (th_in - cw_lo) / in_w;
    float om    = th * (1.0f - th);
    float den   = delta + (d_k1 + d_k - 2.0f * delta) * om;
    float num   = in_h * (delta * th * th + d_k * om);
    float outv  = ch_lo + num / den;

    float omt = 1.0f - th;
    float dn  = delta * delta * (d_k1 * th * th + 2.0f * delta * om + d_k * omt * omt);
    float lad = logf(dn) - 2.0f * logf(den);

    if (l == 0) {
        out[row]     = outv;
        out[B + row] = lad;
    }
}

// ---------------- prep: split W1^T, W2^T into bf16 hi/lo [n][k] pairs ----------------
__global__ void prep_kernel(const float* __restrict__ W1, const float* __restrict__ W2)
{
    int i = blockIdx.x * blockDim.x + threadIdx.x;
    if (i < NH * NFEAT / 2) {
        int n = i >> 5, kp = i & 31;
        float w0 = W1[(2 * kp)     * NH + n];
        float w1 = W1[(2 * kp + 1) * NH + n];
        g_W1T_hi[i] = pack_hi(w0, w1);
        g_W1T_lo[i] = pack_lo(w0, w1);
    }
    int j = i - NH * NFEAT / 2;
    if (j >= 0 && j < NP * NH / 2) {
        int n = j >> 7, kp = j & 127;
        float w0 = W2[(2 * kp)     * NP + n];
        float w1 = W2[(2 * kp + 1) * NP + n];
        g_W2T_hi[j] = pack_hi(w0, w1);
        g_W2T_lo[j] = pack_lo(w0, w1);
    }
}

// ---------------- persistent fused kernel ----------------
__global__ __launch_bounds__(NT, 1)
void cyl_pers_kernel(const float* __restrict__ theta,
                     const float* __restrict__ xc,
                     const float* __restrict__ b1,
                     const float* __restrict__ b2,
                     const float* __restrict__ eta,
                     float* __restrict__ out,
                     int B, int ntiles)
{
    extern __shared__ char smem[];
    const uint32_t smb = smem_u32(smem);
    const int t = threadIdx.x;
    const int w = t >> 5;          // 0..15
    const int l = t & 31;

    // ---- one-time weight + bias staging ----
    for (int i = t; i < NH * NFEAT / 2; i += NT) {
        int n = i >> 5, kp = i & 31;
        uint32_t off = SWZ128(n * 128 + kp * 4);
        *(uint32_t*)(smem + SM_W1H + off) = g_W1T_hi[i];
        *(uint32_t*)(smem + SM_W1L + off) = g_W1T_lo[i];
    }
    for (int i = t; i < NP * NH / 2; i += NT) {
        int n = i >> 7, kp = i & 127;
        uint32_t off = SWZ512(n * 512 + kp * 4);
        *(uint32_t*)(smem + SM_W2H + off) = g_W2T_hi[i];
        *(uint32_t*)(smem + SM_W2L + off) = g_W2T_lo[i];
    }
    if (t < NH) ((float*)(smem + SM_B1))[t] = b1[t];
    if (t < NP) ((float*)(smem + SM_B2))[t] = b2[t];
    const float e0 = eta[0];

    // lane address components
    const int l4 = l & 15;
    const uint32_t a128 = (uint32_t)(l4 * 128 + ((l >> 4) & 1) * 16);
    const uint32_t b128 = (uint32_t)((l & 7) * 128 + ((l >> 3) & 1) * 16);
    const uint32_t a512 = (uint32_t)(l4 * 512 + ((l >> 4) & 1) * 16);
    const uint32_t b512 = (uint32_t)((l & 7) * 512 + ((l >> 3) & 1) * 16);
    const int rq = l >> 2, cq = 2 * (l & 3);

    // stage-1 mapping: 2 m-groups x 8 col-groups (all 16 warps)
    const int w8 = w & 7, mt = w >> 3;
    // stage-2 mapping (warps 0..7): rows [mgA*16,+16), cols [ngA*24,+24), full k
    const int mgA = (w >> 2) & 1, ngA = w & 3;
    // group B (warps 8..15)
    const int wb  = w - 8;
    const int tb  = wb * 32 + l;    // 0..255 within group B

    const float2* xp = (const float2*)xc;

    // ---- pre-loop: stage first X tile (all threads) ----
    {
        int tile0 = blockIdx.x;
        #pragma unroll
        for (int j = 0; j < 2; j++) {
            int i = t + j * NT;
            if (i < TM * 32) {
                int r = i >> 5, kp = i & 31;
                int row = tile0 * TM + r;
                float2 v = (row < B) ? xp[row * 32 + kp] : make_float2(0.f, 0.f);
                uint32_t off = SWZ128(r * 128 + kp * 4);
                *(uint32_t*)(smem + SM_X + off)        = pack_hi(v.x, v.y);
                *(uint32_t*)(smem + SM_X + 4096 + off) = pack_lo(v.x, v.y);
            }
        }
    }
    __syncthreads();

    int it = 0;
    int last_row0 = -1, last_par = 0;
    for (int tile = blockIdx.x; tile < ntiles; tile += gridDim.x, it++) {
        const int par  = it & 1;
        const int row0 = tile * TM;
        const int ntile = tile + gridDim.x;
        const bool have_next = ntile < ntiles;
        float* ppcur = (float*)(smem + (par ? SM_PP1 : SM_PP0));

        // ================= phase 1: stage 1 (all 16 warps) =================
        {
            float P1[4][4], Q1[4][4];
            #pragma unroll
            for (int n = 0; n < 4; n++)
                #pragma unroll
                for (int q = 0; q < 4; q++) { P1[n][q] = 0.f; Q1[n][q] = 0.f; }

            #pragma unroll
            for (int k = 0; k < 4; k++) {
                uint32_t Ah[4], Al[4];
                uint32_t o = a128 + (uint32_t)(mt * 2048 + k * 32);
                ldsm_x4(smb + SM_X +        SWZ128(o), Ah);
                ldsm_x4(smb + SM_X + 4096 + SWZ128(o), Al);
                #pragma unroll
                for (int n = 0; n < 4; n++) {
                    uint32_t Bh[2], Bl[2];
                    uint32_t ob = b128 + (uint32_t)((w8 * 32 + n * 8) * 128 + k * 32);
                    ldsm_x2(smb + SM_W1H + SWZ128(ob), Bh);
                    ldsm_x2(smb + SM_W1L + SWZ128(ob), Bl);
                    mma16816(P1[n], Ah, Bh);
                    mma16816(Q1[n], Ah, Bl);
                    mma16816(Q1[n], Al, Bh);
                }
            }

            // epilogue 1: h = relu(C1 + b1) -> bf16 hi/lo smem (SWZ512)
            const float* b1s = (const float*)(smem + SM_B1);
            #pragma unroll
            for (int n = 0; n < 4; n++) {
                int col = w8 * 32 + n * 8 + cq;
                float bb0 = b1s[col], bb1 = b1s[col + 1];
                int r0 = mt * 16 + rq;
                float v0 = fmaxf(P1[n][0] + Q1[n][0] + bb0, 0.f);
                float v1 = fmaxf(P1[n][1] + Q1[n][1] + bb1, 0.f);
                float v2 = fmaxf(P1[n][2] + Q1[n][2] + bb0, 0.f);
                float v3 = fmaxf(P1[n][3] + Q1[n][3] + bb1, 0.f);
                uint32_t o0 = SWZ512(r0 * 512 + col * 2);
                uint32_t o1 = SWZ512((r0 + 8) * 512 + col * 2);
                *(uint32_t*)(smem + SM_HH + o0) = pack_hi(v0, v1);
                *(uint32_t*)(smem + SM_HL + o0) = pack_lo(v0, v1);
                *(uint32_t*)(smem + SM_HH + o1) = pack_hi(v2, v3);
                *(uint32_t*)(smem + SM_HL + o1) = pack_lo(v2, v3);
            }
        }
        __syncthreads();   // h visible; X consumed; pp[par^1] spline of it-1... (see below)

        // ================= phase 2 =================
        if (w < 8) {
            // ---- group A: stage 2 full-k + epilogue -> pp[par] ----
            float P2[3][4], Q2[3][4];
            #pragma unroll
            for (int n = 0; n < 3; n++)
                #pragma unroll
                for (int q = 0; q < 4; q++) { P2[n][q] = 0.f; Q2[n][q] = 0.f; }

            #pragma unroll 4
            for (int k = 0; k < 16; k++) {
                uint32_t Ah[4], Al[4];
                uint32_t oa = a512 + (uint32_t)(mgA * 8192 + k * 32);
                ldsm_x4(smb + SM_HH + SWZ512(oa), Ah);
                ldsm_x4(smb + SM_HL + SWZ512(oa), Al);
                #pragma unroll
                for (int n = 0; n < 3; n++) {
                    uint32_t Bh[2], Bl[2];
                    uint32_t ob = b512 + (uint32_t)((ngA * 24 + n * 8) * 512 + k * 32);
                    ldsm_x2(smb + SM_W2H + SWZ512(ob), Bh);
                    ldsm_x2(smb + SM_W2L + SWZ512(ob), Bl);
                    mma16816(P2[n], Ah, Bh);
                    mma16816(Q2[n], Ah, Bl);
                    mma16816(Q2[n], Al, Bh);
                }
            }

            const float* b2s = (const float*)(smem + SM_B2);
            #pragma unroll
            for (int n = 0; n < 3; n++) {
                int col = ngA * 24 + n * 8 + cq;
                float bb0 = b2s[col], bb1 = b2s[col + 1];
                int r0 = mgA * 16 + rq;
                ppcur[r0 * PS + col]           = (P2[n][0] + Q2[n][0] + bb0) * e0;
                ppcur[r0 * PS + col + 1]       = (P2[n][1] + Q2[n][1] + bb1) * e0;
                ppcur[(r0 + 8) * PS + col]     = (P2[n][2] + Q2[n][2] + bb0) * e0;
                ppcur[(r0 + 8) * PS + col + 1] = (P2[n][3] + Q2[n][3] + bb1) * e0;
            }
        } else {
            // ---- group B: stage next X + spline of previous tile ----
            float2 xv[4];
            if (have_next) {   // issue LDGs first, consume after spline
                #pragma unroll
                for (int j = 0; j < 4; j++) {
                    int i = tb + j * 256;
                    int r = i >> 5, kp = i & 31;
                    int row = ntile * TM + r;
                    xv[j] = (row < B) ? xp[row * 32 + kp] : make_float2(0.f, 0.f);
                }
            }

            if (it > 0) {
                const float* ppprev = (const float*)(smem + (par ? SM_PP0 : SM_PP1));
                int prow0 = row0 - gridDim.x * TM;
                #pragma unroll
                for (int j = 0; j < 4; j++) {
                    int rr = wb + 8 * j;
                    int row = prow0 + rr;
                    if (row < B)
                        spline_row(ppprev, rr, row, l, theta, out, B);
                }
            }

            if (have_next) {
                #pragma unroll
                for (int j = 0; j < 4; j++) {
                    int i = tb + j * 256;
                    int r = i >> 5, kp = i & 31;
                    uint32_t off = SWZ128(r * 128 + kp * 4);
                    *(uint32_t*)(smem + SM_X + off)        = pack_hi(xv[j].x, xv[j].y);
                    *(uint32_t*)(smem + SM_X + 4096 + off) = pack_lo(xv[j].x, xv[j].y);
                }
            }
        }
        __syncthreads();   // pp[par] complete; X staged; h consumed

        last_row0 = row0;
        last_par  = par;
    }

    // ---- drain: spline of the final tile (all 16 warps, 2 rows each) ----
    if (last_row0 >= 0) {
        const float* pplast = (const float*)(smem + (last_par ? SM_PP1 : SM_PP0));
        #pragma unroll
        for (int j = 0; j < 2; j++) {
            int rr = w + 16 * j;
            int row = last_row0 + rr;
            if (row < B)
                spline_row(pplast, rr, row, l, theta, out, B);
        }
    }
}

extern "C" void kernel_launch(void* const* d_in, const int* in_sizes, int n_in,
                              void* d_out, int out_size)
{
    const float* theta = (const float*)d_in[0];
    const float* xc    = (const float*)d_in[1];
    const float* W1    = (const float*)d_in[2];
    const float* b1    = (const float*)d_in[3];
    const float* W2    = (const float*)d_in[4];
    const float* b2    = (const float*)d_in[5];
    const float* eta   = (const float*)d_in[6];
    float* out = (float*)d_out;

    int B = in_sizes[0];

    static int nsm = 0;
    if (nsm == 0) {
        cudaDeviceProp prop;
        if (cudaGetDeviceProperties(&prop, 0) == cudaSuccess && prop.multiProcessorCount > 0)
            nsm = prop.multiProcessorCount;
        else
            nsm = 148;
        cudaFuncSetAttribute(cyl_pers_kernel, cudaFuncAttributeMaxDynamicSharedMemorySize, SM_TOTAL);
    }

    int prep_elems = NH * NFEAT / 2 + NP * NH / 2;
    prep_kernel<<<(prep_elems + 255) / 256, 256>>>(W1, W2);

    int ntiles = (B + TM - 1) / TM;
    int grid = nsm < ntiles ? nsm : ntiles;
    cyl_pers_kernel<<<grid, NT, SM_TOTAL>>>(theta, xc, b1, b2, eta, out, B, ntiles);
}

// round 11
// speedup vs baseline: 1.1030x; 1.1030x over previous
#include <cuda_runtime.h>
#include <cuda_bf16.h>
#include <math.h>
#include <stdint.h>

// ---------------- problem constants ----------------
#define NB     32
#define NFEAT  64
#define NH     256
#define NP     96
#define TM     32           // rows per tile
#define NT     512
#define PS     100          // padded row stride (floats) for pp

#define TWO_PI_F   6.2831853071795864769f
#define MIN_WH     1e-3f
#define MIN_D      1e-3f
#define DERIV_OFF  0.5413248546129181f     // log(e-1)
#define SIZE_SCALE (1.0f - 1e-3f * 32.0f)

// ---- smem layout (bytes) ----
#define SM_W1H   0          // W1T hi [256 n][64 k bf16 = 128B rows, SWZ128]  32KB
#define SM_W1L   32768
#define SM_W2H   65536      // W2T hi [96 n][256 k bf16 = 512B rows, SWZ512]  48KB
#define SM_W2L   114688
#define SM_X     163840     // X single buf: hi @0, lo @4096 (SWZ128)          8KB
#define SM_HH    172032     // h hi [32 r][256 bf16, SWZ512]                  16KB
#define SM_HL    188416     // h lo                                           16KB
#define SM_PP0   204800     // spline params f32[32][PS], buffer 0          12.8KB
#define SM_PP1   217600     // buffer 1 (also stage-2 partial scratch)      12.8KB
#define SM_B1    230400     // b1 f32[256]
#define SM_B2    231424     // b2 f32[96]
#define SM_TOTAL 231808

#define SWZ128(o) ((uint32_t)(o) ^ (((uint32_t)(o) >> 3) & 0x70u))
#define SWZ512(o) ((uint32_t)(o) ^ (((uint32_t)(o) >> 5) & 0x70u))

// ---------------- pre-split weights (device globals) ----------------
__device__ uint32_t g_W1T_hi[NH * NFEAT / 2];   // [n][kpair]
__device__ uint32_t g_W1T_lo[NH * NFEAT / 2];
__device__ uint32_t g_W2T_hi[NP * NH / 2];      // [n][kpair]
__device__ uint32_t g_W2T_lo[NP * NH / 2];

// ---------------- helpers ----------------
static __device__ __forceinline__ uint32_t smem_u32(const void* p) {
    uint32_t a;
    asm("{ .reg .u64 t; cvta.to.shared.u64 t, %1; cvt.u32.u64 %0, t; }" : "=r"(a) : "l"(p));
    return a;
}
static __device__ __forceinline__ void ldsm_x4(uint32_t addr, uint32_t r[4]) {
    asm volatile("ldmatrix.sync.aligned.m8n8.x4.shared.b16 {%0,%1,%2,%3}, [%4];"
                 : "=r"(r[0]), "=r"(r[1]), "=r"(r[2]), "=r"(r[3]) : "r"(addr));
}
static __device__ __forceinline__ void ldsm_x2(uint32_t addr, uint32_t r[2]) {
    asm volatile("ldmatrix.sync.aligned.m8n8.x2.shared.b16 {%0,%1}, [%2];"
                 : "=r"(r[0]), "=r"(r[1]) : "r"(addr));
}
static __device__ __forceinline__ void mma16816(float c[4], const uint32_t a[4],
                                                uint32_t b0, uint32_t b1) {
    asm volatile("mma.sync.aligned.m16n8k16.row.col.f32.bf16.bf16.f32 "
                 "{%0,%1,%2,%3}, {%4,%5,%6,%7}, {%8,%9}, {%0,%1,%2,%3};"
                 : "+f"(c[0]), "+f"(c[1]), "+f"(c[2]), "+f"(c[3])
                 : "r"(a[0]), "r"(a[1]), "r"(a[2]), "r"(a[3]), "r"(b0), "r"(b1));
}
static __device__ __forceinline__ uint32_t pack_hi(float v0, float v1) {
    __nv_bfloat16 h0 = __float2bfloat16_rn(v0), h1 = __float2bfloat16_rn(v1);
    return (uint32_t)__bfloat16_as_ushort(h0) | ((uint32_t)__bfloat16_as_ushort(h1) << 16);
}
static __device__ __forceinline__ uint32_t pack_lo(float v0, float v1) {
    __nv_bfloat16 h0 = __float2bfloat16_rn(v0), h1 = __float2bfloat16_rn(v1);
    __nv_bfloat16 l0 = __float2bfloat16_rn(v0 - __bfloat162float(h0));
    __nv_bfloat16 l1 = __float2bfloat16_rn(v1 - __bfloat162float(h1));
    return (uint32_t)__bfloat16_as_ushort(l0) | ((uint32_t)__bfloat16_as_ushort(l1) << 16);
}
static __device__ __forceinline__ float softplus_f(float x) {
    return (x > 0.0f) ? (x + log1pf(expf(-x))) : log1pf(expf(x));
}

// warp-per-row circular RQ spline (lane = bin)
static __device__ __forceinline__ void spline_row(const float* pp, int rr, int row, int l,
                                                  const float* __restrict__ theta,
                                                  float* __restrict__ out, int B)
{
    const unsigned FULL = 0xffffffffu;
    float th_in = theta[row];
    float uw = pp[rr * PS + l];
    float uh = pp[rr * PS + NB + l];
    float ud = pp[rr * PS + 2 * NB + l] + DERIV_OFF;

    float mw = uw, mh = uh;
    #pragma unroll
    for (int o = 16; o; o >>= 1) {
        mw = fmaxf(mw, __shfl_xor_sync(FULL, mw, o));
        mh = fmaxf(mh, __shfl_xor_sync(FULL, mh, o));
    }
    float ew = expf(uw - mw), eh = expf(uh - mh);
    float sw = ew, sh = eh;
    #pragma unroll
    for (int o = 16; o; o >>= 1) {
        sw += __shfl_xor_sync(FULL, sw, o);
        sh += __shfl_xor_sync(FULL, sh, o);
    }
    float szw = MIN_WH + SIZE_SCALE * (ew / sw);
    float szh = MIN_WH + SIZE_SCALE * (eh / sh);

    float cw = szw, chs = szh;
    #pragma unroll
    for (int o = 1; o < 32; o <<= 1) {
        float a = __shfl_up_sync(FULL, cw,  o);
        float b = __shfl_up_sync(FULL, chs, o);
        if (l >= o) { cw += a; chs += b; }
    }

    float kw = (l == 31) ? TWO_PI_F : TWO_PI_F * cw;
    float kh = (l == 31) ? TWO_PI_F : TWO_PI_F * chs;

    unsigned bal = __ballot_sync(FULL, th_in >= kw);
    int bin = __popc(bal);
    if (bin > NB - 1) bin = NB - 1;
    int lo = (bin > 0) ? bin - 1 : 0;

    float cw_hi = __shfl_sync(FULL, kw, bin);
    float cw_lo = __shfl_sync(FULL, kw, lo);
    float ch_hi = __shfl_sync(FULL, kh, bin);
    float ch_lo = __shfl_sync(FULL, kh, lo);
    if (bin == 0) { cw_lo = 0.0f; ch_lo = 0.0f; }

    float in_w = cw_hi - cw_lo;
    float in_h = ch_hi - ch_lo;

    float dsp  = MIN_D + softplus_f(ud);
    float d_k  = __shfl_sync(FULL, dsp, bin);
    float d_k1 = __shfl_sync(FULL, dsp, (bin + 1) & 31);

    float delta = in_h / in_w;
    float th    = (th_in - cw_lo) / in_w;
    float om    = th * (1.0f - th);
    float den   = delta + (d_k1 + d_k - 2.0f * delta) * om;
    float num   = in_h * (delta * th * th + d_k * om);
    float outv  = ch_lo + num / den;

    float omt = 1.0f - th;
    float dn  = delta * delta * (d_k1 * th * th + 2.0f * delta * om + d_k * omt * omt);
    float lad = logf(dn) - 2.0f * logf(den);

    if (l == 0) {
        out[row]     = outv;
        out[B + row] = lad;
    }
}

// ---------------- prep: split W1^T, W2^T into bf16 hi/lo [n][k] pairs ----------------
__global__ void prep_kernel(const float* __restrict__ W1, const float* __restrict__ W2)
{
    int i = blockIdx.x * blockDim.x + threadIdx.x;
    if (i < NH * NFEAT / 2) {
        int n = i >> 5, kp = i & 31;
        float w0 = W1[(2 * kp)     * NH + n];
        float w1 = W1[(2 * kp + 1) * NH + n];
        g_W1T_hi[i] = pack_hi(w0, w1);
        g_W1T_lo[i] = pack_lo(w0, w1);
    }
    int j = i - NH * NFEAT / 2;
    if (j >= 0 && j < NP * NH / 2) {
        int n = j >> 7, kp = j & 127;
        float w0 = W2[(2 * kp)     * NP + n];
        float w1 = W2[(2 * kp + 1) * NP + n];
        g_W2T_hi[j] = pack_hi(w0, w1);
        g_W2T_lo[j] = pack_lo(w0, w1);
    }
}

// ---------------- persistent fused kernel ----------------
__global__ __launch_bounds__(NT, 1)
void cyl_pers_kernel(const float* __restrict__ theta,
                     const float* __restrict__ xc,
                     const float* __restrict__ b1,
                     const float* __restrict__ b2,
                     const float* __restrict__ eta,
                     float* __restrict__ out,
                     int B, int ntiles)
{
    extern __shared__ char smem[];
    const uint32_t smb = smem_u32(smem);
    const int t = threadIdx.x;
    const int w = t >> 5;          // 0..15
    const int l = t & 31;

    // ---- one-time weight + bias staging ----
    for (int i = t; i < NH * NFEAT / 2; i += NT) {
        int n = i >> 5, kp = i & 31;
        uint32_t off = SWZ128(n * 128 + kp * 4);
        *(uint32_t*)(smem + SM_W1H + off) = g_W1T_hi[i];
        *(uint32_t*)(smem + SM_W1L + off) = g_W1T_lo[i];
    }
    for (int i = t; i < NP * NH / 2; i += NT) {
        int n = i >> 7, kp = i & 127;
        uint32_t off = SWZ512(n * 512 + kp * 4);
        *(uint32_t*)(smem + SM_W2H + off) = g_W2T_hi[i];
        *(uint32_t*)(smem + SM_W2L + off) = g_W2T_lo[i];
    }
    if (t < NH) ((float*)(smem + SM_B1))[t] = b1[t];
    if (t < NP) ((float*)(smem + SM_B2))[t] = b2[t];
    const float e0 = eta[0];

    // lane address components
    const int l4 = l & 15;
    const uint32_t a128 = (uint32_t)(l4 * 128 + ((l >> 4) & 1) * 16);
    const uint32_t a512 = (uint32_t)(l4 * 512 + ((l >> 4) & 1) * 16);
    // x4 B-operand lane address (2 n-tiles per load)
    const uint32_t b128q = (uint32_t)(((l & 7) + ((l >> 4) & 1) * 8) * 128 + ((l >> 3) & 1) * 16);
    const uint32_t b512q = (uint32_t)(((l & 7) + ((l >> 4) & 1) * 8) * 512 + ((l >> 3) & 1) * 16);
    const uint32_t b512  = (uint32_t)((l & 7) * 512 + ((l >> 3) & 1) * 16);
    const int rq = l >> 2, cq = 2 * (l & 3);

    // stage-1 mapping: 2 m-groups x 8 col-groups
    const int w8 = w & 7, mt = w >> 3;
    // stage-2 mapping: kslice x mg x ng
    const int ks = w >> 3, mg = (w >> 2) & 1, ng = w & 3;

    const float2* xp = (const float2*)xc;

    // ---- pre-loop: stage first X tile ----
    {
        int tile0 = blockIdx.x;
        if (t < TM * 32) {
            int r = t >> 5, kp = t & 31;
            int row = tile0 * TM + r;
            float2 v = (row < B) ? xp[row * 32 + kp] : make_float2(0.f, 0.f);
            uint32_t off = SWZ128(r * 128 + kp * 4);
            *(uint32_t*)(smem + SM_X + off)        = pack_hi(v.x, v.y);
            *(uint32_t*)(smem + SM_X + 4096 + off) = pack_lo(v.x, v.y);
        }
        int i2 = t + NT;
        if (i2 < TM * 32) {
            int r = i2 >> 5, kp = i2 & 31;
            int row = tile0 * TM + r;
            float2 v = (row < B) ? xp[row * 32 + kp] : make_float2(0.f, 0.f);
            uint32_t off = SWZ128(r * 128 + kp * 4);
            *(uint32_t*)(smem + SM_X + off)        = pack_hi(v.x, v.y);
            *(uint32_t*)(smem + SM_X + 4096 + off) = pack_lo(v.x, v.y);
        }
    }
    __syncthreads();

    int it = 0;
    int last_row0 = -1, last_par = 0;
    for (int tile = blockIdx.x; tile < ntiles; tile += gridDim.x, it++) {
        const int par  = it & 1;
        const int row0 = tile * TM;
        const int ntile = tile + gridDim.x;
        const bool have_next = ntile < ntiles;
        float* ppcur  = (float*)(smem + (par ? SM_PP1 : SM_PP0));

        // prefetch next X tile into regs (consumed in phase 2)
        float2 xv[2];
        if (have_next) {
            #pragma unroll
            for (int j = 0; j < 2; j++) {
                int i = t + j * NT;
                int r = i >> 5, kp = i & 31;
                int row = ntile * TM + r;
                xv[j] = (row < B) ? xp[row * 32 + kp] : make_float2(0.f, 0.f);
            }
        }

        // ========== phase 1: stage 1 MMA + epi1 + spline(prev) ==========
        {
            float P1[4][4], Q1[4][4];
            #pragma unroll
            for (int n = 0; n < 4; n++)
                #pragma unroll
                for (int q = 0; q < 4; q++) { P1[n][q] = 0.f; Q1[n][q] = 0.f; }

            #pragma unroll
            for (int k = 0; k < 4; k++) {
                uint32_t Ah[4], Al[4];
                uint32_t o = a128 + (uint32_t)(mt * 2048 + k * 32);
                ldsm_x4(smb + SM_X +        SWZ128(o), Ah);
                ldsm_x4(smb + SM_X + 4096 + SWZ128(o), Al);
                #pragma unroll
                for (int np = 0; np < 2; np++) {     // n-tile pairs {0,1}, {2,3}
                    uint32_t Bh[4], Bl[4];
                    uint32_t ob = b128q + (uint32_t)((w8 * 32 + np * 16) * 128 + k * 32);
                    ldsm_x4(smb + SM_W1H + SWZ128(ob), Bh);
                    ldsm_x4(smb + SM_W1L + SWZ128(ob), Bl);
                    mma16816(P1[2*np],   Ah, Bh[0], Bh[1]);
                    mma16816(Q1[2*np],   Ah, Bl[0], Bl[1]);
                    mma16816(Q1[2*np],   Al, Bh[0], Bh[1]);
                    mma16816(P1[2*np+1], Ah, Bh[2], Bh[3]);
                    mma16816(Q1[2*np+1], Ah, Bl[2], Bl[3]);
                    mma16816(Q1[2*np+1], Al, Bh[2], Bh[3]);
                }
            }

            // epilogue 1: h = relu(C1 + b1) -> bf16 hi/lo smem (SWZ512)
            const float* b1s = (const float*)(smem + SM_B1);
            #pragma unroll
            for (int n = 0; n < 4; n++) {
                int col = w8 * 32 + n * 8 + cq;
                float bb0 = b1s[col], bb1 = b1s[col + 1];
                int r0 = mt * 16 + rq;
                float v0 = fmaxf(P1[n][0] + Q1[n][0] + bb0, 0.f);
                float v1 = fmaxf(P1[n][1] + Q1[n][1] + bb1, 0.f);
                float v2 = fmaxf(P1[n][2] + Q1[n][2] + bb0, 0.f);
                float v3 = fmaxf(P1[n][3] + Q1[n][3] + bb1, 0.f);
                uint32_t o0 = SWZ512(r0 * 512 + col * 2);
                uint32_t o1 = SWZ512((r0 + 8) * 512 + col * 2);
                *(uint32_t*)(smem + SM_HH + o0) = pack_hi(v0, v1);
                *(uint32_t*)(smem + SM_HL + o0) = pack_lo(v0, v1);
                *(uint32_t*)(smem + SM_HH + o1) = pack_hi(v2, v3);
                *(uint32_t*)(smem + SM_HL + o1) = pack_lo(v2, v3);
            }
        }

        // spline of PREVIOUS tile (pp[1-par]) — independent of stage-1 state
        if (it > 0) {
            const float* ppprev = (const float*)(smem + (par ? SM_PP0 : SM_PP1));
            int prow0 = row0 - gridDim.x * TM;
            #pragma unroll
            for (int j = 0; j < 2; j++) {
                int rr = w + 16 * j;
                int row = prow0 + rr;
                if (row < B)
                    spline_row(ppprev, rr, row, l, theta, out, B);
            }
        }
        __syncthreads();   // h visible; X consumed; spline(prev) done

        // ========== phase 2: stage 2 MMA (k-split) + partials + X STS ==========
        {
            float P2[3][4], Q2[3][4];
            #pragma unroll
            for (int n = 0; n < 3; n++)
                #pragma unroll
                for (int q = 0; q < 4; q++) { P2[n][q] = 0.f; Q2[n][q] = 0.f; }

            #pragma unroll
            for (int k = 0; k < 8; k++) {
                int kk = ks * 8 + k;
                uint32_t Ah[4], Al[4];
                uint32_t oa = a512 + (uint32_t)(mg * 8192 + kk * 32);
                ldsm_x4(smb + SM_HH + SWZ512(oa), Ah);
                ldsm_x4(smb + SM_HL + SWZ512(oa), Al);
                // n-tiles 0,1 via x4
                {
                    uint32_t Bh[4], Bl[4];
                    uint32_t ob = b512q + (uint32_t)((ng * 24) * 512 + kk * 32);
                    ldsm_x4(smb + SM_W2H + SWZ512(ob), Bh);
                    ldsm_x4(smb + SM_W2L + SWZ512(ob), Bl);
                    mma16816(P2[0], Ah, Bh[0], Bh[1]);
                    mma16816(Q2[0], Ah, Bl[0], Bl[1]);
                    mma16816(Q2[0], Al, Bh[0], Bh[1]);
                    mma16816(P2[1], Ah, Bh[2], Bh[3]);
                    mma16816(Q2[1], Ah, Bl[2], Bl[3]);
                    mma16816(Q2[1], Al, Bh[2], Bh[3]);
                }
                // n-tile 2 via x2
                {
                    uint32_t Bh[2], Bl[2];
                    uint32_t ob = b512 + (uint32_t)((ng * 24 + 16) * 512 + kk * 32);
                    ldsm_x2(smb + SM_W2H + SWZ512(ob), Bh);
                    ldsm_x2(smb + SM_W2L + SWZ512(ob), Bl);
                    mma16816(P2[2], Ah, Bh[0], Bh[1]);
                    mma16816(Q2[2], Ah, Bl[0], Bl[1]);
                    mma16816(Q2[2], Al, Bh[0], Bh[1]);
                }
            }

            // kslice-1 warps: dump partials into pp[par] (stale region)
            if (ks == 1) {
                #pragma unroll
                for (int n = 0; n < 3; n++) {
                    int col = ng * 24 + n * 8 + cq;
                    int r0 = mg * 16 + rq;
                    ppcur[r0 * PS + col]           = P2[n][0] + Q2[n][0];
                    ppcur[r0 * PS + col + 1]       = P2[n][1] + Q2[n][1];
                    ppcur[(r0 + 8) * PS + col]     = P2[n][2] + Q2[n][2];
                    ppcur[(r0 + 8) * PS + col + 1] = P2[n][3] + Q2[n][3];
                }
            }

            // stash ks0 results in registers across the barrier
            if (ks == 0) {
                // keep P2/Q2 live into phase 3 (compiler keeps them in regs)
                // store next X tile (X consumed in phase 1)
                if (have_next) {
                    #pragma unroll
                    for (int j = 0; j < 2; j++) {
                        int i = t + j * NT;
                        int r = i >> 5, kp = i & 31;
                        uint32_t off = SWZ128(r * 128 + kp * 4);
                        *(uint32_t*)(smem + SM_X + off)        = pack_hi(xv[j].x, xv[j].y);
                        *(uint32_t*)(smem + SM_X + 4096 + off) = pack_lo(xv[j].x, xv[j].y);
                    }
                }
                __syncthreads();   // partials visible

                // phase 3 work fused here for ks0: reduce + epilogue 2
                const float* b2s = (const float*)(smem + SM_B2);
                #pragma unroll
                for (int n = 0; n < 3; n++) {
                    int col = ng * 24 + n * 8 + cq;
                    float bb0 = b2s[col], bb1 = b2s[col + 1];
                    int r0 = mg * 16 + rq;
                    float s0 = P2[n][0] + Q2[n][0] + ppcur[r0 * PS + col];
                    float s1 = P2[n][1] + Q2[n][1] + ppcur[r0 * PS + col + 1];
                    float s2 = P2[n][2] + Q2[n][2] + ppcur[(r0 + 8) * PS + col];
                    float s3 = P2[n][3] + Q2[n][3] + ppcur[(r0 + 8) * PS + col + 1];
                    ppcur[r0 * PS + col]           = (s0 + bb0) * e0;
                    ppcur[r0 * PS + col + 1]       = (s1 + bb1) * e0;
                    ppcur[(r0 + 8) * PS + col]     = (s2 + bb0) * e0;
                    ppcur[(r0 + 8) * PS + col + 1] = (s3 + bb1) * e0;
                }
            } else {
                if (have_next) {
                    #pragma unroll
                    for (int j = 0; j < 2; j++) {
                        int i = t + j * NT;
                        int r = i >> 5, kp = i & 31;
                        uint32_t off = SWZ128(r * 128 + kp * 4);
                        *(uint32_t*)(smem + SM_X + off)        = pack_hi(xv[j].x, xv[j].y);
                        *(uint32_t*)(smem + SM_X + 4096 + off) = pack_lo(xv[j].x, xv[j].y);
                    }
                }
                __syncthreads();   // matching barrier (partials visible)
            }
        }
        __syncthreads();   // pp[par] final; X staged

        last_row0 = row0;
        last_par  = par;
    }

    // ---- drain: spline of the final tile ----
    if (last_row0 >= 0) {
        const float* pplast = (const float*)(smem + (last_par ? SM_PP1 : SM_PP0));
        #pragma unroll
        for (int j = 0; j < 2; j++) {
            int rr = w + 16 * j;
            int row = last_row0 + rr;
            if (row < B)
                spline_row(pplast, rr, row, l, theta, out, B);
        }
    }
}

extern "C" void kernel_launch(void* const* d_in, const int* in_sizes, int n_in,
                              void* d_out, int out_size)
{
    const float* theta = (const float*)d_in[0];
    const float* xc    = (const float*)d_in[1];
    const float* W1    = (const float*)d_in[2];
    const float* b1    = (const float*)d_in[3];
    const float* W2    = (const float*)d_in[4];
    const float* b2    = (const float*)d_in[5];
    const float* eta   = (const float*)d_in[6];
    float* out = (float*)d_out;

    int B = in_sizes[0];

    static int nsm = 0;
    if (nsm == 0) {
        cudaDeviceProp prop;
        if (cudaGetDeviceProperties(&prop, 0) == cudaSuccess && prop.multiProcessorCount > 0)
            nsm = prop.multiProcessorCount;
        else
            nsm = 148;
        cudaFuncSetAttribute(cyl_pers_kernel, cudaFuncAttributeMaxDynamicSharedMemorySize, SM_TOTAL);
    }

    int prep_elems = NH * NFEAT / 2 + NP * NH / 2;
    prep_kernel<<<(prep_elems + 255) / 256, 256>>>(W1, W2);

    int ntiles = (B + TM - 1) / TM;
    int grid = nsm < ntiles ? nsm : ntiles;
    cyl_pers_kernel<<<grid, NT, SM_TOTAL>>>(theta, xc, b1, b2, eta, out, B, ntiles);
}